// round 7
// baseline (speedup 1.0000x reference)
#include <cuda_runtime.h>
#include <math.h>
#include <stdint.h>

#define BB 16
#define CC 3
#define TT 32
#define HH 224
#define WW 224
#define GS 32
#define GH 7
#define GW 7
#define NPF 49
#define NODES 1568
#define NPATCH 25088
#define NPP 3072
#define NEDGE 15962
#define XFLOATS 250880
#define CAP 96

#define PBAR() asm volatile("bar.sync %0, %1;" :: "r"(pair + 1), "r"(64) : "memory")

__device__ __forceinline__ float wsumf(float x) {
    #pragma unroll
    for (int o = 16; o; o >>= 1) x += __shfl_xor_sync(0xffffffffu, x, o);
    return x;
}
__device__ __forceinline__ int wsumi(int x) {
    #pragma unroll
    for (int o = 16; o; o >>= 1) x += __shfl_xor_sync(0xffffffffu, x, o);
    return x;
}
__device__ __forceinline__ float wminf(float x) {
    #pragma unroll
    for (int o = 16; o; o >>= 1) x = fminf(x, __shfl_xor_sync(0xffffffffu, x, o));
    return x;
}
__device__ __forceinline__ float wmaxf(float x) {
    #pragma unroll
    for (int o = 16; o; o >>= 1) x = fmaxf(x, __shfl_xor_sync(0xffffffffu, x, o));
    return x;
}

// warp-uniform count of elements < piv over the whole 3072-float smem patch
__device__ __forceinline__ int count_less(const float* sp, int lane, float piv) {
    int c = 0;
    #pragma unroll 4
    for (int m = 0; m < 24; m++) {
        float4 x4 = *reinterpret_cast<const float4*>(sp + m * 128 + lane * 4);
        c += (x4.x < piv) + (x4.y < piv) + (x4.z < piv) + (x4.w < piv);
    }
    return wsumi(c);
}

// gather elements in [glo, ghi) into buf (clamped at cap); returns true in-range count
__device__ __forceinline__ int gather_range(const float* sp, float* buf, int lane,
                                            float glo, float ghi, int cap) {
    int cnt = 0;
    unsigned lt = (1u << lane) - 1u;
    #pragma unroll 2
    for (int m = 0; m < 24; m++) {
        float4 x4 = *reinterpret_cast<const float4*>(sp + m * 128 + lane * 4);
        float xs[4] = {x4.x, x4.y, x4.z, x4.w};
        #pragma unroll
        for (int e = 0; e < 4; e++) {
            float x = xs[e];
            bool inb = (x >= glo) && (x < ghi);
            unsigned mk = __ballot_sync(0xffffffffu, inb);
            if (inb) {
                int pos = cnt + __popc(mk & lt);
                if (pos < cap) buf[pos] = x;
            }
            cnt += __popc(mk);
        }
    }
    return cnt;
}

// tie-aware exact select of two ranks rr0, rr1 (0-based) within buf[0..cnt)
__device__ __forceinline__ void select2(const float* buf, int cnt, int rr0, int rr1,
                                        int lane, float* o0, float* o1) {
    float a0 = 0.f, a1 = 0.f;
    bool f0 = false, f1 = false;
    for (int idx = lane; idx < cnt; idx += 32) {
        float v = buf[idx];
        int less = 0, eq = 0;
        for (int m = 0; m < cnt; m++) {
            float c = buf[m];
            less += (c < v);
            eq   += (c == v);
        }
        if (rr0 >= less && rr0 < less + eq) { a0 = v; f0 = true; }
        if (rr1 >= less && rr1 < less + eq) { a1 = v; f1 = true; }
    }
    unsigned m0 = __ballot_sync(0xffffffffu, f0);
    unsigned m1 = __ballot_sync(0xffffffffu, f1);
    int s0 = m0 ? (__ffs(m0) - 1) : 0;
    int s1 = m1 ? (__ffs(m1) - 1) : 0;
    *o0 = __shfl_sync(0xffffffffu, a0, s0);
    *o1 = __shfl_sync(0xffffffffu, a1, s1);
}

// guaranteed-exact single-rank selection via value bisection (rare; warp-local)
__device__ float select_slow(const float* sp, float* buf, int lane, int k,
                             float mn, float mx) {
    float lo = mn, hi = nextafterf(mx, INFINITY);
    int clo = 0;
    for (int it = 0; it < 80; it++) {
        int ch = count_less(sp, lane, hi);
        int cnt = ch - clo;
        if (cnt <= CAP) {
            int g = gather_range(sp, buf, lane, lo, hi, CAP);
            __syncwarp();
            float r0, r1;
            select2(buf, g < CAP ? g : CAP, k - clo, k - clo, lane, &r0, &r1);
            return r0;
        }
        float mid = 0.5f * (lo + hi);
        if (!(mid > lo && mid < hi)) return lo;   // 1-ulp interval: all equal
        int cm = count_less(sp, lane, mid);
        if (k < cm) hi = mid; else { lo = mid; clo = cm; }
    }
    return lo;
}

__global__ void __launch_bounds__(128, 8)
feat_kernel(const float* __restrict__ v, float* __restrict__ out)
{
    __shared__ __align__(16) float patch[2][NPP];
    __shared__ float cbuf[2][3][CAP];
    __shared__ float redf[2][2][6];
    __shared__ int   redi[2][2][6];
    __shared__ int   dcur[2][3];
    __shared__ float resv[2][5];

    const int tid  = threadIdx.x;
    const int lane = tid & 31;
    const int warp = tid >> 5;
    const int pair = warp >> 1;       // patch within block
    const int wip  = warp & 1;        // warp within pair
    const int tp   = (wip << 5) | lane;   // 0..63

    const int p = blockIdx.x * 2 + pair;  // ((b*TT+t)*GH+i)*GW+j
    const int j = p % GW;
    int tmp = p / GW;
    const int i = tmp % GH;
    tmp /= GH;
    const int t = tmp % TT;
    const int b = tmp / TT;

    float* sp = patch[pair];

    // ---- load 3072 floats (12 float4/thread, coalesced): moments+min/max+smem ----
    float S1 = 0.f, S2 = 0.f, S3 = 0.f, S4 = 0.f;
    float mn = INFINITY, mx = -INFINITY;
    #pragma unroll 4
    for (int k = 0; k < 12; k++) {
        int f = tp + k * 64;              // float4 index 0..767
        int row = f >> 3, sub = f & 7;
        int c = row >> 5, y = row & 31;
        size_t base = ((((size_t)b * CC + c) * TT + t) * HH + (size_t)(i * GS + y)) * WW
                      + (size_t)(j * GS) + (size_t)(sub * 4);
        float4 x4 = *reinterpret_cast<const float4*>(v + base);
        float xs[4] = {x4.x, x4.y, x4.z, x4.w};
        #pragma unroll
        for (int e = 0; e < 4; e++) {
            float x = xs[e];
            float x2 = x * x;
            S1 += x; S2 += x2; S3 += x2 * x; S4 += x2 * x2;
            mn = fminf(mn, x);
            mx = fmaxf(mx, x);
        }
        *reinterpret_cast<float4*>(sp + f * 4) = x4;
    }
    S1 = wsumf(S1); S2 = wsumf(S2); S3 = wsumf(S3); S4 = wsumf(S4);
    mn = wminf(mn); mx = wmaxf(mx);
    if (lane == 0) {
        redf[pair][wip][0] = S1; redf[pair][wip][1] = S2;
        redf[pair][wip][2] = S3; redf[pair][wip][3] = S4;
        redf[pair][wip][4] = mn; redf[pair][wip][5] = mx;
    }
    PBAR();
    S1 = redf[pair][0][0] + redf[pair][1][0];
    S2 = redf[pair][0][1] + redf[pair][1][1];
    S3 = redf[pair][0][2] + redf[pair][1][2];
    S4 = redf[pair][0][3] + redf[pair][1][3];
    mn = fminf(redf[pair][0][4], redf[pair][1][4]);
    mx = fmaxf(redf[pair][0][5], redf[pair][1][5]);

    const float meanf = S1 * (1.0f / (float)NPP);
    const float sdf = sqrtf(fmaxf((S2 - (float)NPP * meanf * meanf) / ((float)NPP - 1.f), 0.f));

    const float Z0 = -0.67448975f, Z2 = 0.67448975f;
    const int RA0 = 767, RB0 = 768, RA1 = 1535, RA2 = 2303, RB2 = 2304;

    // ---- pass 1: count below 6 pivots over this warp's 48 elems; pair-combine ----
    float plo0, phi0, plo1, phi1, plo2, phi2;
    int cl0, ch0, cl1, ch1, cl2, ch2;
    {
        float D = 0.12f;
        bool ok = false;
        for (int att = 0; att < 8 && !ok; att++) {
            if (att < 4) {
                plo0 = meanf + (Z0 - D) * sdf; phi0 = meanf + (Z0 + D) * sdf;
                plo1 = meanf + (-D) * sdf;     phi1 = meanf + (D) * sdf;
                plo2 = meanf + (Z2 - D) * sdf; phi2 = meanf + (Z2 + D) * sdf;
            } else {
                float hiall = nextafterf(mx, INFINITY);
                plo0 = plo1 = plo2 = mn;
                phi0 = phi1 = phi2 = hiall;
            }
            int a0 = 0, b0 = 0, a1 = 0, b1 = 0, a2 = 0, b2 = 0;
            #pragma unroll 3
            for (int m = 0; m < 12; m++) {
                float4 x4 = *reinterpret_cast<const float4*>(sp + (tp + m * 64) * 4);
                float xs[4] = {x4.x, x4.y, x4.z, x4.w};
                #pragma unroll
                for (int e = 0; e < 4; e++) {
                    float x = xs[e];
                    a0 += (x < plo0); b0 += (x < phi0);
                    a1 += (x < plo1); b1 += (x < phi1);
                    a2 += (x < plo2); b2 += (x < phi2);
                }
            }
            a0 = wsumi(a0); b0 = wsumi(b0); a1 = wsumi(a1);
            b1 = wsumi(b1); a2 = wsumi(a2); b2 = wsumi(b2);
            if (lane == 0) {
                redi[pair][wip][0] = a0; redi[pair][wip][1] = b0;
                redi[pair][wip][2] = a1; redi[pair][wip][3] = b1;
                redi[pair][wip][4] = a2; redi[pair][wip][5] = b2;
            }
            PBAR();
            cl0 = redi[pair][0][0] + redi[pair][1][0];
            ch0 = redi[pair][0][1] + redi[pair][1][1];
            cl1 = redi[pair][0][2] + redi[pair][1][2];
            ch1 = redi[pair][0][3] + redi[pair][1][3];
            cl2 = redi[pair][0][4] + redi[pair][1][4];
            ch2 = redi[pair][0][5] + redi[pair][1][5];
            ok = (cl0 <= RA0 && ch0 > RB0) && (cl1 <= RA1 && ch1 > RA1)
              && (cl2 <= RA2 && ch2 > RB2);
            PBAR();
            if (!ok) D *= 2.0f;
        }
    }

    // ---- interpolate tight windows (~±22 ranks) ----
    float glo0, ghi0, glo1, ghi1, glo2, ghi2;
    {
        float w0 = phi0 - plo0, w1 = phi1 - plo1, w2 = phi2 - plo2;
        float ci0 = (float)(ch0 - cl0), ci1 = (float)(ch1 - cl1), ci2 = (float)(ch2 - cl2);
        float v0 = plo0 + (768.0f  - (float)cl0) / ci0 * w0;
        float v1 = plo1 + (1535.5f - (float)cl1) / ci1 * w1;
        float v2 = plo2 + (2304.0f - (float)cl2) / ci2 * w2;
        float d0 = 22.f * w0 / ci0, d1 = 22.f * w1 / ci1, d2 = 22.f * w2 / ci2;
        glo0 = v0 - d0; ghi0 = v0 + d0;
        glo1 = v1 - d1; ghi1 = v1 + d1;
        glo2 = v2 - d2; ghi2 = v2 + d2;
    }

    if (tp < 3) dcur[pair][tp] = 0;
    PBAR();

    // ---- pass 2: fused count(<glo) + atomic gather into 3 region buffers ----
    int c2l0 = 0, c2l1 = 0, c2l2 = 0;
    #pragma unroll 3
    for (int m = 0; m < 12; m++) {
        float4 x4 = *reinterpret_cast<const float4*>(sp + (tp + m * 64) * 4);
        float xs[4] = {x4.x, x4.y, x4.z, x4.w};
        #pragma unroll
        for (int e = 0; e < 4; e++) {
            float x = xs[e];
            bool l0 = x < glo0; c2l0 += l0;
            if (!l0 && x < ghi0) {
                int pos = atomicAdd(&dcur[pair][0], 1);
                if (pos < CAP) cbuf[pair][0][pos] = x;
            }
            bool l1 = x < glo1; c2l1 += l1;
            if (!l1 && x < ghi1) {
                int pos = atomicAdd(&dcur[pair][1], 1);
                if (pos < CAP) cbuf[pair][1][pos] = x;
            }
            bool l2 = x < glo2; c2l2 += l2;
            if (!l2 && x < ghi2) {
                int pos = atomicAdd(&dcur[pair][2], 1);
                if (pos < CAP) cbuf[pair][2][pos] = x;
            }
        }
    }
    c2l0 = wsumi(c2l0); c2l1 = wsumi(c2l1); c2l2 = wsumi(c2l2);
    if (lane == 0) {
        redi[pair][wip][0] = c2l0; redi[pair][wip][1] = c2l1; redi[pair][wip][2] = c2l2;
    }
    PBAR();
    c2l0 = redi[pair][0][0] + redi[pair][1][0];
    c2l1 = redi[pair][0][1] + redi[pair][1][1];
    c2l2 = redi[pair][0][2] + redi[pair][1][2];
    const int g0 = dcur[pair][0], g1 = dcur[pair][1], g2 = dcur[pair][2];

    // ---- exact selects: warp0 -> region0; warp1 -> regions 1,2 ----
    if (wip == 0) {
        float q0, q1;
        if (g0 <= CAP && RA0 >= c2l0 && RB0 < c2l0 + g0) {
            select2(cbuf[pair][0], g0, RA0 - c2l0, RB0 - c2l0, lane, &q0, &q1);
        } else {
            q0 = select_slow(sp, cbuf[pair][0], lane, RA0, mn, mx);
            q1 = select_slow(sp, cbuf[pair][0], lane, RB0, mn, mx);
        }
        if (lane == 0) { resv[pair][0] = q0; resv[pair][1] = q1; }
    } else {
        float q2, q3, q4, dum;
        if (g1 <= CAP && RA1 >= c2l1 && RA1 < c2l1 + g1) {
            select2(cbuf[pair][1], g1, RA1 - c2l1, RA1 - c2l1, lane, &q2, &dum);
        } else {
            q2 = select_slow(sp, cbuf[pair][1], lane, RA1, mn, mx);
        }
        if (g2 <= CAP && RA2 >= c2l2 && RB2 < c2l2 + g2) {
            select2(cbuf[pair][2], g2, RA2 - c2l2, RB2 - c2l2, lane, &q3, &q4);
        } else {
            q3 = select_slow(sp, cbuf[pair][2], lane, RA2, mn, mx);
            q4 = select_slow(sp, cbuf[pair][2], lane, RB2, mn, mx);
        }
        if (lane == 0) { resv[pair][2] = q2; resv[pair][3] = q3; resv[pair][4] = q4; }
    }
    PBAR();

    if (tp == 0) {
        const double n = (double)NPP;
        double s1 = S1, s2 = S2, s3 = S3, s4 = S4;
        double mean = s1 / n;
        double c2 = s2 - n * mean * mean;
        double c3 = s3 - 3.0 * mean * s2 + 2.0 * n * mean * mean * mean;
        double m2s = mean * mean;
        double c4 = s4 - 4.0 * mean * s3 + 6.0 * m2s * s2 - 3.0 * n * m2s * m2s;
        double sd = sqrt(c2 / (n - 1.0));
        double sde = sd + 1e-8;
        double energy = s2 / n;
        double rms = sqrt(energy + 1e-8);
        double i3 = 1.0 / (sde * sde * sde);
        double skew = (c3 / n) * i3;
        double kurt = (c4 / n) * i3 / sde - 3.0;
        float q25 = resv[pair][0] * 0.25f + resv[pair][1] * 0.75f;
        float q75 = resv[pair][3] * 0.75f + resv[pair][4] * 0.25f;

        float* o = out + (size_t)p * 10;
        o[0] = (float)mean; o[1] = (float)sd; o[2] = mn; o[3] = mx;
        o[4] = (float)energy; o[5] = (float)rms; o[6] = (float)skew;
        o[7] = (float)kurt; o[8] = resv[pair][2]; o[9] = q75 - q25;
    }
}

__device__ __forceinline__ int tau_t(int t) {
    int c = 0;
    if (t + 1 < TT) c++;
    if (t - 1 >= 0) c++;
    if (t + 2 < TT) c++;
    if (t - 2 >= 0) c++;
    return c;
}

__global__ void edge_kernel(float* __restrict__ out)
{
    int node = blockIdx.x * blockDim.x + threadIdx.x;
    if (node >= NODES) return;
    int t = node / NPF;
    int rem = node % NPF;
    int i = rem / GW;
    int j = rem % GW;

    int mt = t < 30 ? t : 30;
    int cum_tau = (t > 0 ? 2 : 0) + (t > 1 ? 3 : 0)
                + 4 * (mt > 2 ? (mt - 2) : 0) + (t > 30 ? 3 : 0);
    int taut = tau_t(t);
    int rowpref = (i == 0) ? 0 : (31 + 50 * (i - 1));
    int ci = (i == 0 || i == GH - 1) ? 2 : 3;
    int cumcj = (j > 0 ? 2 : 0) + 3 * (j > 1 ? (j - 1) : 0);
    int sp = rowpref + ci * cumcj - j;
    int off = 312 * t + 49 * cum_tau + sp + rem * taut;

    const int di[8] = {-1,-1,-1, 0, 0, 1, 1, 1};
    const int dj[8] = {-1, 0, 1,-1, 1,-1, 0, 1};
    int e = off;
    float fnode = (float)node;
    #pragma unroll
    for (int q = 0; q < 8; q++) {
        int ni = i + di[q], nj = j + dj[q];
        if (ni >= 0 && ni < GH && nj >= 0 && nj < GW) {
            out[e]         = fnode;
            out[NEDGE + e] = (float)(t * NPF + ni * GW + nj);
            e++;
        }
    }
    const int dts[4] = {1, -1, 2, -2};
    #pragma unroll
    for (int q = 0; q < 4; q++) {
        int tt2 = t + dts[q];
        if (tt2 >= 0 && tt2 < TT) {
            out[e]         = fnode;
            out[NEDGE + e] = (float)(tt2 * NPF + i * GW + j);
            e++;
        }
    }
}

extern "C" void kernel_launch(void* const* d_in, const int* in_sizes, int n_in,
                              void* d_out, int out_size)
{
    const float* video = (const float*)d_in[0];
    float* out = (float*)d_out;

    if (out_size >= XFLOATS + 2 * NEDGE) {
        edge_kernel<<<(NODES + 255) / 256, 256>>>(out + XFLOATS);
    }
    feat_kernel<<<NPATCH / 2, 128>>>(video, out);
}